// round 3
// baseline (speedup 1.0000x reference)
#include <cuda_runtime.h>

#define N_NODES  50000
#define N_EDGES  1600000
#define N_GRAPHS 512
#define EMB      32
#define HID      64

// ---------------- scratch (device globals: allocation-free) ----------------
__device__ float g_x   [N_NODES * EMB];   // embedded node features
__device__ float g_agg1[N_NODES * EMB];   // layer-1 neighbor sums
__device__ float g_h1  [N_NODES * HID];   // layer-1 output
__device__ float g_agg2[N_NODES * HID];   // layer-2 neighbor sums
__device__ float g_deg [N_NODES];         // in-degree (shared by both layers)
__device__ float g_psum[N_GRAPHS * HID];  // pooled sums
__device__ float g_pcnt[N_GRAPHS];        // pooled counts

__device__ __forceinline__ void red_add_v4(float* p, float4 v) {
    asm volatile("red.global.add.v4.f32 [%0], {%1,%2,%3,%4};"
                 :: "l"(p), "f"(v.x), "f"(v.y), "f"(v.z), "f"(v.w) : "memory");
}
__device__ __forceinline__ void red_add_f(float* p, float v) {
    asm volatile("red.global.add.f32 [%0], %1;" :: "l"(p), "f"(v) : "memory");
}

// ---------------- init: zero scratch + embedding gather ----------------
__global__ void k_init(const int* __restrict__ x_ids,
                       const float* __restrict__ embed) {
    int stride = gridDim.x * blockDim.x;
    int tid = blockIdx.x * blockDim.x + threadIdx.x;

    float4* agg1 = reinterpret_cast<float4*>(g_agg1);
    float4* xv   = reinterpret_cast<float4*>(g_x);
    const float4* emb4 = reinterpret_cast<const float4*>(embed);
    const int n1 = N_NODES * EMB / 4;              // 8 float4 per node
    for (int i = tid; i < n1; i += stride) {
        agg1[i] = make_float4(0.f, 0.f, 0.f, 0.f);
        int node = i >> 3;
        int c    = i & 7;
        xv[i] = emb4[(x_ids[node] << 3) + c];
    }
    float4* agg2 = reinterpret_cast<float4*>(g_agg2);
    const int n2 = N_NODES * HID / 4;
    for (int i = tid; i < n2; i += stride) agg2[i] = make_float4(0.f, 0.f, 0.f, 0.f);
    for (int i = tid; i < N_NODES; i += stride) g_deg[i] = 0.f;
    for (int i = tid; i < N_GRAPHS * HID; i += stride) g_psum[i] = 0.f;
    for (int i = tid; i < N_GRAPHS; i += stride) g_pcnt[i] = 0.f;
}

// ---------------- layer-1 edge scatter: 8 threads / edge (EMB=32) ----------------
__global__ void k_scatter1(const int* __restrict__ src, const int* __restrict__ dst) {
    int gid = blockIdx.x * blockDim.x + threadIdx.x;
    if (gid >= N_EDGES * 8) return;
    int e = gid >> 3;
    int c = gid & 7;
    int s = src[e];
    int d = dst[e];
    float4 v = reinterpret_cast<const float4*>(g_x)[(s << 3) + c];
    red_add_v4(&g_agg1[(d << 5) + (c << 2)], v);
    if (c == 0) red_add_f(&g_deg[d], 1.f);
}

// ---------------- layer-1 node update: warp / node ----------------
__global__ void k_update1(const float* __restrict__ w_l,
                          const float* __restrict__ b,
                          const float* __restrict__ w_r) {
    __shared__ float s_wl[EMB * HID];
    __shared__ float s_wr[EMB * HID];
    __shared__ float s_b[HID];
    int t = threadIdx.x;
    for (int i = t; i < EMB * HID; i += blockDim.x) { s_wl[i] = w_l[i]; s_wr[i] = w_r[i]; }
    if (t < HID) s_b[t] = b[t];
    __syncthreads();

    int node = (blockIdx.x * blockDim.x + t) >> 5;
    int lane = t & 31;
    if (node >= N_NODES) return;

    float inv = 1.f / fmaxf(g_deg[node], 1.f);
    float a0 = s_b[lane], a1 = s_b[lane + 32];
    const float* am = g_agg1 + node * EMB;
    const float* ax = g_x    + node * EMB;
#pragma unroll
    for (int k = 0; k < EMB; k++) {
        float m  = am[k] * inv;
        float xv = ax[k];
        a0 = fmaf(m, s_wl[k * HID + lane],      fmaf(xv, s_wr[k * HID + lane],      a0));
        a1 = fmaf(m, s_wl[k * HID + lane + 32], fmaf(xv, s_wr[k * HID + lane + 32], a1));
    }
    g_h1[node * HID + lane]      = fmaxf(a0, 0.f);
    g_h1[node * HID + lane + 32] = fmaxf(a1, 0.f);
}

// ---------------- layer-2 edge scatter: 16 threads / edge (HID=64) ----------------
__global__ void k_scatter2(const int* __restrict__ src, const int* __restrict__ dst) {
    int gid = blockIdx.x * blockDim.x + threadIdx.x;
    if (gid >= N_EDGES * 16) return;
    int e = gid >> 4;
    int c = gid & 15;
    int s = src[e];
    int d = dst[e];
    float4 v = reinterpret_cast<const float4*>(g_h1)[(s << 4) + c];
    red_add_v4(&g_agg2[(d << 6) + (c << 2)], v);
}

// ---------------- layer-2 node update + pool accumulation: warp / node ----------------
__global__ void k_update2(const int* __restrict__ batch,
                          const float* __restrict__ w_l,
                          const float* __restrict__ b,
                          const float* __restrict__ w_r) {
    __shared__ float s_wl[HID * HID];
    __shared__ float s_wr[HID * HID];
    __shared__ float s_b[HID];
    int t = threadIdx.x;
    for (int i = t; i < HID * HID; i += blockDim.x) { s_wl[i] = w_l[i]; s_wr[i] = w_r[i]; }
    if (t < HID) s_b[t] = b[t];
    __syncthreads();

    int node = (blockIdx.x * blockDim.x + t) >> 5;
    int lane = t & 31;
    if (node >= N_NODES) return;

    float inv = 1.f / fmaxf(g_deg[node], 1.f);
    float a0 = s_b[lane], a1 = s_b[lane + 32];
    const float* am = g_agg2 + node * HID;
    const float* ah = g_h1   + node * HID;
#pragma unroll
    for (int k = 0; k < HID; k++) {
        float m = am[k] * inv;
        float h = ah[k];
        a0 = fmaf(m, s_wl[k * HID + lane],      fmaf(h, s_wr[k * HID + lane],      a0));
        a1 = fmaf(m, s_wl[k * HID + lane + 32], fmaf(h, s_wr[k * HID + lane + 32], a1));
    }
    a0 = fmaxf(a0, 0.f);
    a1 = fmaxf(a1, 0.f);

    int g = batch[node];
    red_add_f(&g_psum[g * HID + lane],      a0);
    red_add_f(&g_psum[g * HID + lane + 32], a1);
    if (lane == 0) red_add_f(&g_pcnt[g], 1.f);
}

// ---------------- final: pooled mean @ w_out + b_out ----------------
__global__ void k_final(const float* __restrict__ w_out,
                        const float* __restrict__ b_out,
                        float* __restrict__ out) {
    int g = blockIdx.x * blockDim.x + threadIdx.x;
    if (g >= N_GRAPHS) return;
    float inv = 1.f / fmaxf(g_pcnt[g], 1.f);
    float o0 = b_out[0], o1 = b_out[1];
#pragma unroll
    for (int k = 0; k < HID; k++) {
        float p = g_psum[g * HID + k] * inv;
        o0 = fmaf(p, w_out[k * 2],     o0);
        o1 = fmaf(p, w_out[k * 2 + 1], o1);
    }
    out[g * 2]     = o0;
    out[g * 2 + 1] = o1;
}

extern "C" void kernel_launch(void* const* d_in, const int* in_sizes, int n_in,
                              void* d_out, int out_size) {
    const int*   x_ids = (const int*)d_in[0];
    const int*   edge  = (const int*)d_in[1];
    const int*   src   = edge;
    const int*   dst   = edge + N_EDGES;
    const int*   batch = (const int*)d_in[2];
    const float* embed = (const float*)d_in[3];
    const float* w1_l  = (const float*)d_in[4];
    const float* b1    = (const float*)d_in[5];
    const float* w1_r  = (const float*)d_in[6];
    const float* w2_l  = (const float*)d_in[7];
    const float* b2    = (const float*)d_in[8];
    const float* w2_r  = (const float*)d_in[9];
    const float* w_out = (const float*)d_in[10];
    const float* b_out = (const float*)d_in[11];
    float* out = (float*)d_out;

    k_init<<<2048, 256>>>(x_ids, embed);
    k_scatter1<<<(N_EDGES * 8 + 255) / 256, 256>>>(src, dst);
    k_update1<<<(N_NODES + 7) / 8, 256>>>(w1_l, b1, w1_r);
    k_scatter2<<<(N_EDGES * 16 + 255) / 256, 256>>>(src, dst);
    k_update2<<<(N_NODES + 7) / 8, 256>>>(batch, w2_l, b2, w2_r);
    k_final<<<2, 256>>>(w_out, b_out, out);
}

// round 5
// speedup vs baseline: 1.2598x; 1.2598x over previous
#include <cuda_runtime.h>

#define N_NODES  50000
#define N_EDGES  1600000
#define N_GRAPHS 512
#define EMB      32
#define HID      64
#define SCAN_NB  ((N_NODES + 255) / 256)   // 196

// ---------------- scratch (device globals: allocation-free) ----------------
__device__ float g_x   [N_NODES * EMB];   // embedded node features
__device__ float g_h1  [N_NODES * HID];   // layer-1 output
__device__ int   g_cnt [N_NODES];         // in-degree
__device__ int   g_ptr [N_NODES];         // CSR row starts
__device__ int   g_cur [N_NODES];         // fill cursors
__device__ int   g_nbr [N_EDGES];         // CSR adjacency (src node per slot)
__device__ int   g_bsum[256];             // scan block sums
__device__ float g_psum[N_GRAPHS * HID];  // pooled sums
__device__ float g_pcnt[N_GRAPHS];        // pooled counts

__device__ __forceinline__ void red_add_f(float* p, float v) {
    asm volatile("red.global.add.f32 [%0], %1;" :: "l"(p), "f"(v) : "memory");
}

// ---------------- init: zero counters + embedding gather ----------------
__global__ void k_init(const int* __restrict__ x_ids,
                       const float* __restrict__ embed) {
    int stride = gridDim.x * blockDim.x;
    int tid = blockIdx.x * blockDim.x + threadIdx.x;

    float4* xv = reinterpret_cast<float4*>(g_x);
    const float4* emb4 = reinterpret_cast<const float4*>(embed);
    const int n1 = N_NODES * EMB / 4;              // 8 float4 per node
    for (int i = tid; i < n1; i += stride) {
        int node = i >> 3;
        int c    = i & 7;
        xv[i] = emb4[(x_ids[node] << 3) + c];
    }
    for (int i = tid; i < N_NODES; i += stride) g_cnt[i] = 0;
    for (int i = tid; i < N_GRAPHS * HID; i += stride) g_psum[i] = 0.f;
    for (int i = tid; i < N_GRAPHS; i += stride) g_pcnt[i] = 0.f;
}

// ---------------- CSR build: histogram, scan, fill ----------------
__global__ void k_hist(const int* __restrict__ dst) {
    int e = blockIdx.x * blockDim.x + threadIdx.x;
    if (e < N_EDGES) atomicAdd(&g_cnt[dst[e]], 1);
}

__global__ void k_scan1() {
    __shared__ int sh[256];
    int t = threadIdx.x;
    int i = blockIdx.x * 256 + t;
    int v = (i < N_NODES) ? g_cnt[i] : 0;
    sh[t] = v;
    __syncthreads();
#pragma unroll
    for (int off = 1; off < 256; off <<= 1) {
        int x = (t >= off) ? sh[t - off] : 0;
        __syncthreads();
        sh[t] += x;
        __syncthreads();
    }
    if (i < N_NODES) g_ptr[i] = sh[t] - v;   // exclusive within block
    if (t == 255) g_bsum[blockIdx.x] = sh[255];
}

__global__ void k_scan2() {
    __shared__ int sh[256];
    int t = threadIdx.x;
    int v = (t < SCAN_NB) ? g_bsum[t] : 0;
    sh[t] = v;
    __syncthreads();
#pragma unroll
    for (int off = 1; off < 256; off <<= 1) {
        int x = (t >= off) ? sh[t - off] : 0;
        __syncthreads();
        sh[t] += x;
        __syncthreads();
    }
    if (t < SCAN_NB) g_bsum[t] = sh[t] - v;  // exclusive block offsets
}

__global__ void k_scan3() {
    int i = blockIdx.x * 256 + threadIdx.x;
    if (i < N_NODES) {
        int p = g_ptr[i] + g_bsum[blockIdx.x];
        g_ptr[i] = p;
        g_cur[i] = p;
    }
}

__global__ void k_fill(const int* __restrict__ src, const int* __restrict__ dst) {
    int e = blockIdx.x * blockDim.x + threadIdx.x;
    if (e < N_EDGES) {
        int p = atomicAdd(&g_cur[dst[e]], 1);
        g_nbr[p] = src[e];
    }
}

// ---------------- layer 1: gather-mean + SAGE linear + ReLU (fused) ----------------
// warp per node (grid-stride); lane = channel; matvec via warp shuffles
__global__ void __launch_bounds__(256)
k_layer1(const float* __restrict__ w_l,
         const float* __restrict__ b,
         const float* __restrict__ w_r) {
    __shared__ float s_wl[EMB * HID];
    __shared__ float s_wr[EMB * HID];
    __shared__ float s_b[HID];
    int t = threadIdx.x;
    for (int i = t; i < EMB * HID; i += blockDim.x) { s_wl[i] = w_l[i]; s_wr[i] = w_r[i]; }
    if (t < HID) s_b[t] = b[t];
    __syncthreads();

    int lane   = t & 31;
    int warp_g = (blockIdx.x * blockDim.x + t) >> 5;
    int nwarps = (gridDim.x * blockDim.x) >> 5;

    for (int node = warp_g; node < N_NODES; node += nwarps) {
        int beg = g_ptr[node];
        int n   = g_cnt[node];
        float s0 = 0.f, s1 = 0.f, s2 = 0.f, s3 = 0.f;
        int k = 0;
        for (; k + 3 < n; k += 4) {
            int n0 = __ldg(&g_nbr[beg + k]);
            int n1 = __ldg(&g_nbr[beg + k + 1]);
            int n2 = __ldg(&g_nbr[beg + k + 2]);
            int n3 = __ldg(&g_nbr[beg + k + 3]);
            s0 += __ldg(&g_x[n0 * EMB + lane]);
            s1 += __ldg(&g_x[n1 * EMB + lane]);
            s2 += __ldg(&g_x[n2 * EMB + lane]);
            s3 += __ldg(&g_x[n3 * EMB + lane]);
        }
        for (; k < n; k++) s0 += __ldg(&g_x[__ldg(&g_nbr[beg + k]) * EMB + lane]);
        float m  = (s0 + s1) + (s2 + s3);
        m *= (n > 0) ? (1.f / (float)n) : 0.f;       // mean (deg=0 -> 0)
        float xv = g_x[node * EMB + lane];

        float a0 = s_b[lane], a1 = s_b[lane + 32];
#pragma unroll
        for (int kk = 0; kk < EMB; kk++) {
            float mk = __shfl_sync(0xffffffffu, m,  kk);
            float xk = __shfl_sync(0xffffffffu, xv, kk);
            a0 = fmaf(mk, s_wl[kk * HID + lane],      fmaf(xk, s_wr[kk * HID + lane],      a0));
            a1 = fmaf(mk, s_wl[kk * HID + lane + 32], fmaf(xk, s_wr[kk * HID + lane + 32], a1));
        }
        g_h1[node * HID + lane]      = fmaxf(a0, 0.f);
        g_h1[node * HID + lane + 32] = fmaxf(a1, 0.f);
    }
}

// ---------------- layer 2: gather-mean + SAGE linear + ReLU + pool (fused) ----------------
__global__ void __launch_bounds__(256)
k_layer2(const int* __restrict__ batch,
         const float* __restrict__ w_l,
         const float* __restrict__ b,
         const float* __restrict__ w_r) {
    __shared__ float s_wl[HID * HID];
    __shared__ float s_wr[HID * HID];
    __shared__ float s_b[HID];
    int t = threadIdx.x;
    for (int i = t; i < HID * HID; i += blockDim.x) { s_wl[i] = w_l[i]; s_wr[i] = w_r[i]; }
    if (t < HID) s_b[t] = b[t];
    __syncthreads();

    int lane   = t & 31;
    int warp_g = (blockIdx.x * blockDim.x + t) >> 5;
    int nwarps = (gridDim.x * blockDim.x) >> 5;

    for (int node = warp_g; node < N_NODES; node += nwarps) {
        int beg = g_ptr[node];
        int n   = g_cnt[node];
        float m0a = 0.f, m1a = 0.f, m0b = 0.f, m1b = 0.f;
        int k = 0;
        for (; k + 1 < n; k += 2) {
            int n0 = __ldg(&g_nbr[beg + k]);
            int n1 = __ldg(&g_nbr[beg + k + 1]);
            m0a += __ldg(&g_h1[n0 * HID + lane]);
            m1a += __ldg(&g_h1[n0 * HID + lane + 32]);
            m0b += __ldg(&g_h1[n1 * HID + lane]);
            m1b += __ldg(&g_h1[n1 * HID + lane + 32]);
        }
        for (; k < n; k++) {
            int nb = __ldg(&g_nbr[beg + k]);
            m0a += __ldg(&g_h1[nb * HID + lane]);
            m1a += __ldg(&g_h1[nb * HID + lane + 32]);
        }
        float inv = (n > 0) ? (1.f / (float)n) : 0.f;
        float m0 = (m0a + m0b) * inv;
        float m1 = (m1a + m1b) * inv;
        float h0 = g_h1[node * HID + lane];
        float h1 = g_h1[node * HID + lane + 32];

        float a0 = s_b[lane], a1 = s_b[lane + 32];
#pragma unroll
        for (int kk = 0; kk < 32; kk++) {
            float mk = __shfl_sync(0xffffffffu, m0, kk);
            float hk = __shfl_sync(0xffffffffu, h0, kk);
            a0 = fmaf(mk, s_wl[kk * HID + lane],      fmaf(hk, s_wr[kk * HID + lane],      a0));
            a1 = fmaf(mk, s_wl[kk * HID + lane + 32], fmaf(hk, s_wr[kk * HID + lane + 32], a1));
        }
#pragma unroll
        for (int kk = 0; kk < 32; kk++) {
            float mk = __shfl_sync(0xffffffffu, m1, kk);
            float hk = __shfl_sync(0xffffffffu, h1, kk);
            int  ch  = kk + 32;
            a0 = fmaf(mk, s_wl[ch * HID + lane],      fmaf(hk, s_wr[ch * HID + lane],      a0));
            a1 = fmaf(mk, s_wl[ch * HID + lane + 32], fmaf(hk, s_wr[ch * HID + lane + 32], a1));
        }
        a0 = fmaxf(a0, 0.f);
        a1 = fmaxf(a1, 0.f);

        int g = batch[node];
        red_add_f(&g_psum[g * HID + lane],      a0);
        red_add_f(&g_psum[g * HID + lane + 32], a1);
        if (lane == 0) red_add_f(&g_pcnt[g], 1.f);
    }
}

// ---------------- final: pooled mean @ w_out + b_out ----------------
__global__ void k_final(const float* __restrict__ w_out,
                        const float* __restrict__ b_out,
                        float* __restrict__ out) {
    int g = blockIdx.x * blockDim.x + threadIdx.x;
    if (g >= N_GRAPHS) return;
    float inv = 1.f / fmaxf(g_pcnt[g], 1.f);
    float o0 = b_out[0], o1 = b_out[1];
#pragma unroll
    for (int k = 0; k < HID; k++) {
        float p = g_psum[g * HID + k] * inv;
        o0 = fmaf(p, w_out[k * 2],     o0);
        o1 = fmaf(p, w_out[k * 2 + 1], o1);
    }
    out[g * 2]     = o0;
    out[g * 2 + 1] = o1;
}

extern "C" void kernel_launch(void* const* d_in, const int* in_sizes, int n_in,
                              void* d_out, int out_size) {
    const int*   x_ids = (const int*)d_in[0];
    const int*   edge  = (const int*)d_in[1];
    const int*   src   = edge;
    const int*   dst   = edge + N_EDGES;
    const int*   batch = (const int*)d_in[2];
    const float* embed = (const float*)d_in[3];
    const float* w1_l  = (const float*)d_in[4];
    const float* b1    = (const float*)d_in[5];
    const float* w1_r  = (const float*)d_in[6];
    const float* w2_l  = (const float*)d_in[7];
    const float* b2    = (const float*)d_in[8];
    const float* w2_r  = (const float*)d_in[9];
    const float* w_out = (const float*)d_in[10];
    const float* b_out = (const float*)d_in[11];
    float* out = (float*)d_out;

    k_init<<<1024, 256>>>(x_ids, embed);
    k_hist<<<(N_EDGES + 255) / 256, 256>>>(dst);
    k_scan1<<<SCAN_NB, 256>>>();
    k_scan2<<<1, 256>>>();
    k_scan3<<<SCAN_NB, 256>>>();
    k_fill<<<(N_EDGES + 255) / 256, 256>>>(src, dst);
    k_layer1<<<1184, 256>>>(w1_l, b1, w1_r);          // 8 blocks/SM, 16KB smem
    k_layer2<<<1036, 256>>>(batch, w2_l, b2, w2_r);   // 7 blocks/SM, 32KB smem
    k_final<<<2, 256>>>(w_out, b_out, out);
}